// round 2
// baseline (speedup 1.0000x reference)
#include <cuda_runtime.h>
#include <cuda_bf16.h>

#define N_NODES  100000
#define N_EDGES  1600000
#define N_GRAPHS 1000
#define D        128
#define NOUT     6
#define NB_SCAN  ((N_NODES + 1023) / 1024)   // 98

// ---------------- scratch (static device globals; no allocs allowed) ----------
__device__ __align__(16) float g_bufA[N_NODES * D];
__device__ __align__(16) float g_bufB[N_NODES * D];
__device__ int   g_rowptr[N_NODES + 1];
__device__ int   g_pos[N_NODES];          // doubles as histogram counts
__device__ int   g_col[N_EDGES];
__device__ int   g_bsum[NB_SCAN];
__device__ int   g_bscan[NB_SCAN];
__device__ __align__(16) float g_pooled[N_GRAPHS * D];
__device__ int   g_cnt[N_GRAPHS];
__device__ int   g_flag;                   // 1 = indices are int64, 0 = int32

// ---------------- helpers -----------------------------------------------------
__device__ __forceinline__ long long ld_idx(const void* p, long long i, int wide) {
    return wide ? ((const long long*)p)[i] : (long long)((const int*)p)[i];
}

// detect whether ei is stored as int64 (odd int32 words all zero) or int32
__global__ void k_detect(const void* ei) {
    const int* p = (const int*)ei;
    int wide = 1;
    for (int i = 0; i < 64; i++) {
        if (p[2 * i + 1] != 0) { wide = 0; break; }
    }
    g_flag = wide;
}

__global__ void k_zero_scratch() {
    int i = blockIdx.x * blockDim.x + threadIdx.x;
    int total = N_NODES + N_GRAPHS * D + N_GRAPHS;
    for (; i < total; i += gridDim.x * blockDim.x) {
        if (i < N_NODES) g_pos[i] = 0;
        else if (i < N_NODES + N_GRAPHS * D) g_pooled[i - N_NODES] = 0.0f;
        else g_cnt[i - N_NODES - N_GRAPHS * D] = 0;
    }
}

// histogram of dst
__global__ void k_hist(const void* ei) {
    int wide = g_flag;
    int e = blockIdx.x * blockDim.x + threadIdx.x;
    for (; e < N_EDGES; e += gridDim.x * blockDim.x) {
        int dst = (int)ld_idx(ei, (long long)N_EDGES + e, wide);
        atomicAdd(&g_pos[dst], 1);
    }
}

// block-local inclusive scan
__global__ void k_scan1() {
    __shared__ int s[1024];
    int t = threadIdx.x;
    int i = blockIdx.x * 1024 + t;
    int v = (i < N_NODES) ? g_pos[i] : 0;
    s[t] = v;
    __syncthreads();
    for (int off = 1; off < 1024; off <<= 1) {
        int x = (t >= off) ? s[t - off] : 0;
        __syncthreads();
        s[t] += x;
        __syncthreads();
    }
    if (i < N_NODES) g_rowptr[i + 1] = s[t];
    if (t == 1023) g_bsum[blockIdx.x] = s[1023];
}

__global__ void k_scan2() {
    int run = 0;
    for (int b = 0; b < NB_SCAN; b++) {
        int v = g_bsum[b];
        g_bscan[b] = run;
        run += v;
    }
}

__global__ void k_scan3() {
    int t = threadIdx.x;
    int i = blockIdx.x * 1024 + t;
    if (i < N_NODES) g_rowptr[i + 1] += g_bscan[blockIdx.x];
    if (i == 0) g_rowptr[0] = 0;
}

__global__ void k_fillpos() {
    int i = blockIdx.x * blockDim.x + threadIdx.x;
    for (; i < N_NODES; i += gridDim.x * blockDim.x) g_pos[i] = g_rowptr[i];
}

__global__ void k_fill(const void* ei) {
    int wide = g_flag;
    int e = blockIdx.x * blockDim.x + threadIdx.x;
    for (; e < N_EDGES; e += gridDim.x * blockDim.x) {
        int src = (int)ld_idx(ei, e, wide);
        int dst = (int)ld_idx(ei, (long long)N_EDGES + e, wide);
        int p = atomicAdd(&g_pos[dst], 1);
        g_col[p] = src;
    }
}

// agg[n] = x[n] + sum_{j in N(n)} x[j] ; warp per node, lane handles float4
__global__ void k_agg(const float* __restrict__ in, float* __restrict__ out) {
    int warp = (blockIdx.x * blockDim.x + threadIdx.x) >> 5;
    int lane = threadIdx.x & 31;
    if (warp >= N_NODES) return;
    const float4* in4 = (const float4*)in;
    float4* out4 = (float4*)out;
    float4 acc = in4[(long long)warp * 32 + lane];    // self term
    int beg = g_rowptr[warp], end = g_rowptr[warp + 1];
    for (int j = beg; j < end; j++) {
        int s = g_col[j];
        float4 v = in4[(long long)s * 32 + lane];
        acc.x += v.x; acc.y += v.y; acc.z += v.z; acc.w += v.w;
    }
    out4[(long long)warp * 32 + lane] = acc;
}

// C[M x 128] = A[M x 128] @ W[128 x 128] + bias, optional relu
// block: 256 threads = 16x16, each computes 8x8; M-tile 128, full N, K chunks of 16.
__global__ __launch_bounds__(256, 2)
void k_gemm(const float* __restrict__ A, const float* __restrict__ W,
            const float* __restrict__ bias, float* __restrict__ C, int doRelu) {
    __shared__ float As[16][132];
    __shared__ float Ws[16][132];
    int t = threadIdx.x;
    int blockRow = blockIdx.x * 128;
    int tm = t >> 4, tn = t & 15;
    float acc[8][8];
#pragma unroll
    for (int i = 0; i < 8; i++)
#pragma unroll
        for (int j = 0; j < 8; j++) acc[i][j] = 0.0f;

    for (int k0 = 0; k0 < 128; k0 += 16) {
        // A tile: 128 rows x 16 k, transposed into As[k][row]
#pragma unroll
        for (int it = 0; it < 2; it++) {
            int r = (t >> 2) + it * 64;
            int kk4 = (t & 3) * 4;
            int gr = blockRow + r;
            float4 v = make_float4(0.f, 0.f, 0.f, 0.f);
            if (gr < N_NODES)
                v = *(const float4*)&A[(long long)gr * 128 + k0 + kk4];
            As[kk4 + 0][r] = v.x;
            As[kk4 + 1][r] = v.y;
            As[kk4 + 2][r] = v.z;
            As[kk4 + 3][r] = v.w;
        }
        // W tile: 16 k x 128 n
#pragma unroll
        for (int it = 0; it < 2; it++) {
            int idx = t + it * 256;
            int kk = idx >> 5;
            int n4 = (idx & 31) * 4;
            *(float4*)&Ws[kk][n4] = *(const float4*)&W[(long long)(k0 + kk) * 128 + n4];
        }
        __syncthreads();
#pragma unroll
        for (int kk = 0; kk < 16; kk++) {
            float a[8], b[8];
            *(float4*)&a[0] = *(const float4*)&As[kk][tm * 8];
            *(float4*)&a[4] = *(const float4*)&As[kk][tm * 8 + 4];
            *(float4*)&b[0] = *(const float4*)&Ws[kk][tn * 8];
            *(float4*)&b[4] = *(const float4*)&Ws[kk][tn * 8 + 4];
#pragma unroll
            for (int i = 0; i < 8; i++)
#pragma unroll
                for (int j = 0; j < 8; j++) acc[i][j] += a[i] * b[j];
        }
        __syncthreads();
    }
#pragma unroll
    for (int i = 0; i < 8; i++) {
        int gr = blockRow + tm * 8 + i;
        if (gr >= N_NODES) continue;
#pragma unroll
        for (int j = 0; j < 8; j += 4) {
            int c = tn * 8 + j;
            float4 o;
            o.x = acc[i][j + 0] + bias[c + 0];
            o.y = acc[i][j + 1] + bias[c + 1];
            o.z = acc[i][j + 2] + bias[c + 2];
            o.w = acc[i][j + 3] + bias[c + 3];
            if (doRelu) {
                o.x = fmaxf(o.x, 0.f); o.y = fmaxf(o.y, 0.f);
                o.z = fmaxf(o.z, 0.f); o.w = fmaxf(o.w, 0.f);
            }
            *(float4*)&C[(long long)gr * 128 + c] = o;
        }
    }
}

// per-graph counts
__global__ void k_count(const void* batch) {
    int wide = g_flag;
    int n = blockIdx.x * blockDim.x + threadIdx.x;
    for (; n < N_NODES; n += gridDim.x * blockDim.x) {
        int g = (int)ld_idx(batch, n, wide);
        atomicAdd(&g_cnt[g], 1);
    }
}

// pooled sums: batch is sorted, so accumulate runs in registers and flush on
// graph boundary. 128 threads = one feature each; 512 nodes per block.
#define NODES_PER_BLK 512
__global__ void k_pool(const float* __restrict__ h, const void* batch) {
    int wide = g_flag;
    int f = threadIdx.x;
    int base = blockIdx.x * NODES_PER_BLK;
    int end = base + NODES_PER_BLK;
    if (end > N_NODES) end = N_NODES;
    float run = 0.0f;
    int cur = -1;
    for (int n = base; n < end; n++) {
        int g = (int)ld_idx(batch, n, wide);
        if (g != cur) {
            if (cur >= 0) atomicAdd(&g_pooled[cur * D + f], run);
            cur = g;
            run = 0.0f;
        }
        run += h[(long long)n * D + f];
    }
    if (cur >= 0) atomicAdd(&g_pooled[cur * D + f], run);
}

// out[g] = (pooled[g]/cnt[g]) @ Wlin + blin
__global__ void k_final(const float* __restrict__ Wlin, const float* __restrict__ blin,
                        float* __restrict__ out) {
    int g = blockIdx.x;
    int k = threadIdx.x; // 128
    float c = (float)g_cnt[g];
    if (c < 1.0f) c = 1.0f;
    float v = g_pooled[g * D + k] / c;
    __shared__ float red[128];
    for (int j = 0; j < NOUT; j++) {
        red[k] = v * Wlin[k * NOUT + j];
        __syncthreads();
        for (int s = 64; s > 0; s >>= 1) {
            if (k < s) red[k] += red[k + s];
            __syncthreads();
        }
        if (k == 0) out[g * NOUT + j] = red[0] + blin[j];
        __syncthreads();
    }
}

// ---------------- launch ------------------------------------------------------
extern "C" void kernel_launch(void* const* d_in, const int* in_sizes, int n_in,
                              void* d_out, int out_size) {
    const float* x    = (const float*)d_in[0];
    const void*  ei   = d_in[1];
    const void*  batch= d_in[2];
    const float* W1a  = (const float*)d_in[3];
    const float* b1a  = (const float*)d_in[4];
    const float* W1b  = (const float*)d_in[5];
    const float* b1b  = (const float*)d_in[6];
    const float* W2a  = (const float*)d_in[7];
    const float* b2a  = (const float*)d_in[8];
    const float* W2b  = (const float*)d_in[9];
    const float* b2b  = (const float*)d_in[10];
    const float* Wlin = (const float*)d_in[11];
    const float* blin = (const float*)d_in[12];
    float* out = (float*)d_out;

    float* bufA; cudaGetSymbolAddress((void**)&bufA, g_bufA);
    float* bufB; cudaGetSymbolAddress((void**)&bufB, g_bufB);

    k_detect<<<1, 1>>>(ei);
    k_zero_scratch<<<448, 512>>>();
    k_hist<<<6250, 256>>>(ei);
    k_scan1<<<NB_SCAN, 1024>>>();
    k_scan2<<<1, 1>>>();
    k_scan3<<<NB_SCAN, 1024>>>();
    k_fillpos<<<392, 256>>>();
    k_fill<<<6250, 256>>>(ei);

    const int aggBlocks = (N_NODES * 32 + 255) / 256;   // warp per node, 8 warps/block
    const int gemmBlocks = (N_NODES + 127) / 128;

    // layer 1
    k_agg<<<aggBlocks, 256>>>(x, bufA);
    k_gemm<<<gemmBlocks, 256>>>(bufA, W1a, b1a, bufB, 1);
    k_gemm<<<gemmBlocks, 256>>>(bufB, W1b, b1b, bufA, 1);   // includes outer relu
    // layer 2
    k_agg<<<aggBlocks, 256>>>(bufA, bufB);
    k_gemm<<<gemmBlocks, 256>>>(bufB, W2a, b2a, bufA, 1);
    k_gemm<<<gemmBlocks, 256>>>(bufA, W2b, b2b, bufB, 0);
    // pool + classify
    k_count<<<392, 256>>>(batch);
    k_pool<<<(N_NODES + NODES_PER_BLK - 1) / NODES_PER_BLK, 128>>>(bufB, batch);
    k_final<<<N_GRAPHS, 128>>>(Wlin, blin, out);
}